// round 1
// baseline (speedup 1.0000x reference)
#include <cuda_runtime.h>
#include <cstdint>

// QLoRA linear: out = x @ dequant_nf4(w)^T + 2.0 * (x @ A^T) @ B^T
// Shapes: x[8192, 4096] f32, codes[4096, 4096] i32, absmax[4096, 64] f32,
//         A[16, 4096] f32, B[4096, 16] f32, out[8192, 4096] f32.

#define K_DIM 4096
#define N_DIM 4096
#define R_DIM 16
#define TM 128
#define TN 128
#define BK 32
#define PAD 4          // smem row padding (floats), keeps 16B alignment
#define LDA (TM + PAD) // 132
#define LDB (TN + PAD) // 132

// scratch for lora a-projection (already scaled by 2.0): [8192, 16]
__device__ float g_ax[8192 * R_DIM];

__constant__ float c_nf4[16] = {
    -1.0f, -0.6961928009986877f, -0.5250730514526367f, -0.39491748809814453f,
    -0.28444138169288635f, -0.18477343022823334f, -0.09105003625154495f, 0.0f,
    0.07958029955625534f, 0.16093020141124725f, 0.24611230194568634f,
    0.33791524171829224f, 0.44070982933044434f, 0.5626170039176941f,
    0.7229568362236023f, 1.0f};

// ---------------------------------------------------------------------------
// Kernel 1: g_ax[m, r] = 2.0 * sum_k x[m, k] * A[r, k]
// One block handles 32 rows of x. 256 threads: r = tid%16, ml = tid/16 (0..15)
// covering rows {ml, ml+16}.
// ---------------------------------------------------------------------------
__global__ __launch_bounds__(256) void lora_ax_kernel(
    const float* __restrict__ x, const float* __restrict__ A) {
  __shared__ float Xc[32][65];   // 32 rows x 64 k (+1 pad)
  __shared__ float Ac[64][16];   // k x r

  const int tid = threadIdx.x;
  const int m0 = blockIdx.x * 32;
  const int r = tid & 15;
  const int ml = tid >> 4;

  float acc0 = 0.f, acc1 = 0.f;

  for (int kc = 0; kc < K_DIM; kc += 64) {
    // load x chunk [32][64], coalesced along k
#pragma unroll
    for (int i = 0; i < 8; i++) {
      int idx = tid + i * 256;          // 0..2047
      int row = idx >> 6;
      int col = idx & 63;
      Xc[row][col] = x[(size_t)(m0 + row) * K_DIM + kc + col];
    }
    // load A chunk transposed: Ac[kk][r] = A[r, kc+kk]
#pragma unroll
    for (int i = 0; i < 4; i++) {
      int idx = tid + i * 256;          // 0..1023
      int kk = idx >> 4;
      int rr = idx & 15;
      Ac[kk][rr] = A[rr * K_DIM + kc + kk];
    }
    __syncthreads();

#pragma unroll 8
    for (int kk = 0; kk < 64; kk++) {
      float av = Ac[kk][r];
      acc0 += Xc[ml][kk] * av;
      acc1 += Xc[ml + 16][kk] * av;
    }
    __syncthreads();
  }

  g_ax[(size_t)(m0 + ml) * R_DIM + r] = acc0 * 2.0f;
  g_ax[(size_t)(m0 + ml + 16) * R_DIM + r] = acc1 * 2.0f;
}

// ---------------------------------------------------------------------------
// Kernel 2: fused dequant GEMM + LoRA epilogue.
// C[m, n] = sum_k x[m, k] * nf4[codes[n, k]] * absmax[n, k/64]  + sum_r ax[m,r]*B[n,r]
// Block tile 128x128, BK=32, 256 threads, 8x8 per-thread microtile.
// ---------------------------------------------------------------------------
__global__ __launch_bounds__(256) void qlora_gemm_kernel(
    const float* __restrict__ x, const int* __restrict__ codes,
    const float* __restrict__ absmax, const float* __restrict__ Bw,
    float* __restrict__ out) {
  __shared__ float Xs[BK][LDA];  // transposed: Xs[k][m]
  __shared__ float Ws[BK][LDB];  // transposed: Ws[k][n]
  __shared__ float s_nf4[16];

  const int tid = threadIdx.x;
  const int m0 = blockIdx.y * TM;
  const int n0 = blockIdx.x * TN;
  const int tx = tid & 15;   // n direction
  const int ty = tid >> 4;   // m direction

  if (tid < 16) s_nf4[tid] = c_nf4[tid];
  __syncthreads();

  float acc[8][8];
#pragma unroll
  for (int i = 0; i < 8; i++)
#pragma unroll
    for (int j = 0; j < 8; j++) acc[i][j] = 0.f;

  for (int kt = 0; kt < K_DIM; kt += BK) {
    // --- load X tile: 128 rows x 32 k, float4 along k, store transposed ---
#pragma unroll
    for (int i = 0; i < 4; i++) {
      int idx = tid + i * 256;          // 0..1023 (128 rows x 8 quads)
      int row = idx >> 3;
      int kq = (idx & 7) << 2;
      float4 v = *(const float4*)&x[(size_t)(m0 + row) * K_DIM + kt + kq];
      Xs[kq + 0][row] = v.x;
      Xs[kq + 1][row] = v.y;
      Xs[kq + 2][row] = v.z;
      Xs[kq + 3][row] = v.w;
    }
    // --- load + dequant W tile: 128 rows x 32 k ---
    const int amax_col = kt >> 6;  // one absmax per 64-k block; BK=32 aligned inside
#pragma unroll
    for (int i = 0; i < 4; i++) {
      int idx = tid + i * 256;
      int row = idx >> 3;
      int kq = (idx & 7) << 2;
      int4 c = *(const int4*)&codes[(size_t)(n0 + row) * K_DIM + kt + kq];
      float am = absmax[(n0 + row) * (K_DIM / 64) + amax_col];
      Ws[kq + 0][row] = s_nf4[c.x] * am;
      Ws[kq + 1][row] = s_nf4[c.y] * am;
      Ws[kq + 2][row] = s_nf4[c.z] * am;
      Ws[kq + 3][row] = s_nf4[c.w] * am;
    }
    __syncthreads();

#pragma unroll 4
    for (int kk = 0; kk < BK; kk++) {
      float a[8], b[8];
      *(float4*)&a[0] = *(const float4*)&Xs[kk][ty * 8];
      *(float4*)&a[4] = *(const float4*)&Xs[kk][ty * 8 + 4];
      *(float4*)&b[0] = *(const float4*)&Ws[kk][tx * 8];
      *(float4*)&b[4] = *(const float4*)&Ws[kk][tx * 8 + 4];
#pragma unroll
      for (int i = 0; i < 8; i++)
#pragma unroll
        for (int j = 0; j < 8; j++) acc[i][j] += a[i] * b[j];
    }
    __syncthreads();
  }

  // --- LoRA epilogue: acc[i][j] += sum_r ax[m,r] * B[n,r] (ax pre-scaled) ---
  // Reuse smem, transposed layouts [16][128] with stride 132 for LDS.128 loads.
  float* axsT = &Xs[0][0];  // [r * 132 + mrow]
  float* bsT = &Ws[0][0];   // [r * 132 + ncol]
#pragma unroll
  for (int i = 0; i < 8; i++) {
    int idx = tid + i * 256;            // 0..2047
    int mrow = idx >> 4;
    int r = idx & 15;
    axsT[r * LDA + mrow] = g_ax[(size_t)(m0 + mrow) * R_DIM + r];
  }
#pragma unroll
  for (int i = 0; i < 8; i++) {
    int idx = tid + i * 256;
    int ncol = idx >> 4;
    int r = idx & 15;
    bsT[r * LDB + ncol] = Bw[(size_t)(n0 + ncol) * R_DIM + r];
  }
  __syncthreads();

#pragma unroll
  for (int r = 0; r < R_DIM; r++) {
    float a[8], b[8];
    *(float4*)&a[0] = *(const float4*)&axsT[r * LDA + ty * 8];
    *(float4*)&a[4] = *(const float4*)&axsT[r * LDA + ty * 8 + 4];
    *(float4*)&b[0] = *(const float4*)&bsT[r * LDB + tx * 8];
    *(float4*)&b[4] = *(const float4*)&bsT[r * LDB + tx * 8 + 4];
#pragma unroll
    for (int i = 0; i < 8; i++)
#pragma unroll
      for (int j = 0; j < 8; j++) acc[i][j] += a[i] * b[j];
  }

  // --- store ---
#pragma unroll
  for (int i = 0; i < 8; i++) {
    size_t o = (size_t)(m0 + ty * 8 + i) * N_DIM + n0 + tx * 8;
    float4 v0 = make_float4(acc[i][0], acc[i][1], acc[i][2], acc[i][3]);
    float4 v1 = make_float4(acc[i][4], acc[i][5], acc[i][6], acc[i][7]);
    *(float4*)&out[o] = v0;
    *(float4*)&out[o + 4] = v1;
  }
}

// ---------------------------------------------------------------------------
extern "C" void kernel_launch(void* const* d_in, const int* in_sizes, int n_in,
                              void* d_out, int out_size) {
  const float* x = (const float*)d_in[0];
  const int* codes = (const int*)d_in[1];
  const float* absmax = (const float*)d_in[2];
  const float* A = (const float*)d_in[3];
  const float* Bw = (const float*)d_in[4];
  float* out = (float*)d_out;

  const int M = in_sizes[0] / K_DIM;  // 8192

  lora_ax_kernel<<<M / 32, 256>>>(x, A);

  dim3 grid(N_DIM / TN, M / TM);  // (32, 64)
  qlora_gemm_kernel<<<grid, 256>>>(x, codes, absmax, Bw, out);
}

// round 3
// speedup vs baseline: 2.2930x; 2.2930x over previous
#include <cuda_runtime.h>
#include <cuda_bf16.h>
#include <cstdint>

// QLoRA linear via legacy mma.sync (HMMA) 3xBF16-split GEMM (sm_103 plain target).
// out = x @ dequant_nf4(w)^T + 2.0 * (x @ A^T) @ B^T

#define M_DIM 8192
#define N_DIM 4096
#define K_DIM 4096
#define R_DIM 16
#define TM 128
#define TN 128
#define BK 32
#define NK (K_DIM / BK)

#define ROWB 80              // padded smem row stride (64B data + 16B pad)
#define TILEB (128 * ROWB)   // 10240 B per bf16 tile
#define STAGEB (4 * TILEB)   // Ahi, Alo, Bhi, Blo
#define SMEMB (2 * STAGEB)   // 81920 B, double buffered

// ---- device scratch ----
__device__ float g_ax[M_DIM * R_DIM];
__device__ __nv_bfloat16 g_xhi[(size_t)M_DIM * K_DIM];
__device__ __nv_bfloat16 g_xlo[(size_t)M_DIM * K_DIM];
__device__ __nv_bfloat16 g_whi[(size_t)N_DIM * K_DIM];
__device__ __nv_bfloat16 g_wlo[(size_t)N_DIM * K_DIM];

__constant__ float c_nf4[16] = {
    -1.0f, -0.6961928009986877f, -0.5250730514526367f, -0.39491748809814453f,
    -0.28444138169288635f, -0.18477343022823334f, -0.09105003625154495f, 0.0f,
    0.07958029955625534f, 0.16093020141124725f, 0.24611230194568634f,
    0.33791524171829224f, 0.44070982933044434f, 0.5626170039176941f,
    0.7229568362236023f, 1.0f};

// ---------------------------------------------------------------------------
__device__ __forceinline__ uint32_t smem_u32(const void* p) {
  return (uint32_t)__cvta_generic_to_shared((void*)p);
}

__device__ __forceinline__ void cpa16(uint32_t s, const void* g) {
  asm volatile("cp.async.cg.shared.global [%0], [%1], 16;" :: "r"(s), "l"(g));
}

__device__ __forceinline__ void ldsm4(uint32_t (&r)[4], uint32_t addr) {
  asm volatile(
      "ldmatrix.sync.aligned.m8n8.x4.shared.b16 {%0,%1,%2,%3}, [%4];"
      : "=r"(r[0]), "=r"(r[1]), "=r"(r[2]), "=r"(r[3]) : "r"(addr));
}

__device__ __forceinline__ void mma_bf16(float (&d)[4], const uint32_t (&a)[4],
                                         uint32_t b0, uint32_t b1) {
  asm volatile(
      "mma.sync.aligned.m16n8k16.row.col.f32.bf16.bf16.f32 "
      "{%0,%1,%2,%3}, {%4,%5,%6,%7}, {%8,%9}, {%0,%1,%2,%3};"
      : "+f"(d[0]), "+f"(d[1]), "+f"(d[2]), "+f"(d[3])
      : "r"(a[0]), "r"(a[1]), "r"(a[2]), "r"(a[3]), "r"(b0), "r"(b1));
}

// ---------------------------------------------------------------------------
// Precompute kernels
// ---------------------------------------------------------------------------
__global__ __launch_bounds__(256) void split_x_kernel(
    const float* __restrict__ x) {
  size_t i4 = (size_t)blockIdx.x * 256 + threadIdx.x;
  float4 v = ((const float4*)x)[i4];
  float vv[4] = {v.x, v.y, v.z, v.w};
  __nv_bfloat16 h[4], l[4];
#pragma unroll
  for (int e = 0; e < 4; e++) {
    h[e] = __float2bfloat16_rn(vv[e]);
    l[e] = __float2bfloat16_rn(vv[e] - __bfloat162float(h[e]));
  }
  *(uint2*)&g_xhi[i4 * 4] = *(uint2*)h;
  *(uint2*)&g_xlo[i4 * 4] = *(uint2*)l;
}

__global__ __launch_bounds__(256) void dequant_split_kernel(
    const int* __restrict__ codes, const float* __restrict__ absmax) {
  __shared__ float lut[16];
  if (threadIdx.x < 16) lut[threadIdx.x] = c_nf4[threadIdx.x];
  __syncthreads();
  size_t i4 = (size_t)blockIdx.x * 256 + threadIdx.x;
  int4 c = ((const int4*)codes)[i4];
  size_t e0 = i4 * 4;
  int row = (int)(e0 >> 12);
  int col = (int)(e0 & 4095);
  float am = absmax[row * (K_DIM / 64) + (col >> 6)];
  float w[4] = {lut[c.x] * am, lut[c.y] * am, lut[c.z] * am, lut[c.w] * am};
  __nv_bfloat16 h[4], l[4];
#pragma unroll
  for (int e = 0; e < 4; e++) {
    h[e] = __float2bfloat16_rn(w[e]);
    l[e] = __float2bfloat16_rn(w[e] - __bfloat162float(h[e]));
  }
  *(uint2*)&g_whi[e0] = *(uint2*)h;
  *(uint2*)&g_wlo[e0] = *(uint2*)l;
}

// g_ax[m, r] = 2.0 * sum_k x[m, k] * A[r, k]
__global__ __launch_bounds__(256) void lora_ax_kernel(
    const float* __restrict__ x, const float* __restrict__ A) {
  __shared__ float Xc[32][65];
  __shared__ float Ac[64][16];
  const int tid = threadIdx.x;
  const int m0 = blockIdx.x * 32;
  const int r = tid & 15;
  const int ml = tid >> 4;
  float acc0 = 0.f, acc1 = 0.f;
  for (int kc = 0; kc < K_DIM; kc += 64) {
#pragma unroll
    for (int i = 0; i < 8; i++) {
      int idx = tid + i * 256;
      Xc[idx >> 6][idx & 63] =
          x[(size_t)(m0 + (idx >> 6)) * K_DIM + kc + (idx & 63)];
    }
#pragma unroll
    for (int i = 0; i < 4; i++) {
      int idx = tid + i * 256;
      Ac[idx >> 4][idx & 15] = A[(idx & 15) * K_DIM + kc + (idx >> 4)];
    }
    __syncthreads();
#pragma unroll 8
    for (int kk = 0; kk < 64; kk++) {
      float av = Ac[kk][r];
      acc0 += Xc[ml][kk] * av;
      acc1 += Xc[ml + 16][kk] * av;
    }
    __syncthreads();
  }
  g_ax[(size_t)(m0 + ml) * R_DIM + r] = acc0 * 2.0f;
  g_ax[(size_t)(m0 + ml + 16) * R_DIM + r] = acc1 * 2.0f;
}

// ---------------------------------------------------------------------------
// Main HMMA GEMM
// ---------------------------------------------------------------------------
__device__ __forceinline__ void load_stage(char* st, const __nv_bfloat16* Ah,
                                           const __nv_bfloat16* Al,
                                           const __nv_bfloat16* Bh,
                                           const __nv_bfloat16* Bl, int kt,
                                           int tid) {
  const int chunk = tid & 3;
  const int r0 = tid >> 2;
  const uint32_t sb = smem_u32(st);
#pragma unroll
  for (int p = 0; p < 2; p++) {
    int row = r0 + p * 64;
    size_t go = (size_t)row * K_DIM + kt + chunk * 8;
    uint32_t so = row * ROWB + chunk * 16;
    cpa16(sb + so, Ah + go);
    cpa16(sb + TILEB + so, Al + go);
    cpa16(sb + 2 * TILEB + so, Bh + go);
    cpa16(sb + 3 * TILEB + so, Bl + go);
  }
}

__global__ __launch_bounds__(256, 2) void qlora_mma_kernel(
    const float* __restrict__ Bw, float* __restrict__ out) {
  extern __shared__ char sm[];
  const int tid = threadIdx.x;
  const int wid = tid >> 5;
  const int lane = tid & 31;
  const int n0 = blockIdx.x * TN;
  const int m0 = blockIdx.y * TM;
  const int warp_m0 = (wid >> 2) * 64;   // 2 warps in m
  const int warp_n0 = (wid & 3) * 32;    // 4 warps in n

  const __nv_bfloat16* Ah = g_xhi + (size_t)m0 * K_DIM;
  const __nv_bfloat16* Al = g_xlo + (size_t)m0 * K_DIM;
  const __nv_bfloat16* Bh = g_whi + (size_t)n0 * K_DIM;
  const __nv_bfloat16* Bl = g_wlo + (size_t)n0 * K_DIM;

  float acc[4][4][4];
#pragma unroll
  for (int i = 0; i < 4; i++)
#pragma unroll
    for (int j = 0; j < 4; j++)
#pragma unroll
      for (int e = 0; e < 4; e++) acc[i][j][e] = 0.f;

  // prologue: stages 0,1
  load_stage(sm, Ah, Al, Bh, Bl, 0, tid);
  asm volatile("cp.async.commit_group;" ::: "memory");
  load_stage(sm + STAGEB, Ah, Al, Bh, Bl, BK, tid);
  asm volatile("cp.async.commit_group;" ::: "memory");

  // ldmatrix lane addressing: row = lane%16, 16B-half = lane/16
  const int rl = lane & 15;
  const int chalf = (lane >> 4) * 16;

  for (int k = 0; k < NK; k++) {
    const int b = k & 1;
    char* bb = sm + b * STAGEB;
    const uint32_t sA = smem_u32(bb);
    const uint32_t sAl = sA + TILEB;
    const uint32_t sBh = sA + 2 * TILEB;
    const uint32_t sBl = sA + 3 * TILEB;

    asm volatile("cp.async.wait_group 1;" ::: "memory");
    __syncthreads();

#pragma unroll
    for (int ks = 0; ks < 2; ks++) {
      const int colb = ks * 32 + chalf;
      uint32_t bh[2][4], bl[2][4], af[4][4];
      ldsm4(bh[0], sBh + (warp_n0 + rl) * ROWB + colb);
      ldsm4(bh[1], sBh + (warp_n0 + 16 + rl) * ROWB + colb);
      ldsm4(bl[0], sBl + (warp_n0 + rl) * ROWB + colb);
      ldsm4(bl[1], sBl + (warp_n0 + 16 + rl) * ROWB + colb);
#pragma unroll
      for (int mi = 0; mi < 4; mi++)
        ldsm4(af[mi], sA + (warp_m0 + mi * 16 + rl) * ROWB + colb);
      // Ahi x Bhi + Ahi x Blo
#pragma unroll
      for (int mi = 0; mi < 4; mi++)
#pragma unroll
        for (int ni = 0; ni < 4; ni++) {
          mma_bf16(acc[mi][ni], af[mi], bh[ni >> 1][ni & 1],
                   bh[ni >> 1][2 + (ni & 1)]);
          mma_bf16(acc[mi][ni], af[mi], bl[ni >> 1][ni & 1],
                   bl[ni >> 1][2 + (ni & 1)]);
        }
      // Alo x Bhi
#pragma unroll
      for (int mi = 0; mi < 4; mi++)
        ldsm4(af[mi], sAl + (warp_m0 + mi * 16 + rl) * ROWB + colb);
#pragma unroll
      for (int mi = 0; mi < 4; mi++)
#pragma unroll
        for (int ni = 0; ni < 4; ni++)
          mma_bf16(acc[mi][ni], af[mi], bh[ni >> 1][ni & 1],
                   bh[ni >> 1][2 + (ni & 1)]);
    }

    __syncthreads();
    if (k + 2 < NK)
      load_stage(bb, Ah, Al, Bh, Bl, (k + 2) * BK, tid);
    asm volatile("cp.async.commit_group;" ::: "memory");
  }

  // ---- epilogue: LoRA + store ----
  asm volatile("cp.async.wait_all;" ::: "memory");
  __syncthreads();

  float* axs = (float*)sm;                    // [128][16]
  float* bs = (float*)(sm + 128 * 16 * 4);    // [128] stride 17
  for (int j = tid; j < TM * R_DIM; j += 256) axs[j] = g_ax[(size_t)m0 * R_DIM + j];
  for (int j = tid; j < TN * R_DIM; j += 256) {
    int col = j >> 4, r = j & 15;
    bs[col * 17 + r] = Bw[(size_t)(n0 + col) * R_DIM + r];
  }
  __syncthreads();

  const int r0 = lane >> 2;
  const int cbase = warp_n0 + (lane & 3) * 2;
#pragma unroll
  for (int mi = 0; mi < 4; mi++) {
#pragma unroll
    for (int half = 0; half < 2; half++) {
      const int mr = warp_m0 + mi * 16 + r0 + half * 8;
      float axr[16];
      *(float4*)&axr[0] = *(const float4*)&axs[mr * 16];
      *(float4*)&axr[4] = *(const float4*)&axs[mr * 16 + 4];
      *(float4*)&axr[8] = *(const float4*)&axs[mr * 16 + 8];
      *(float4*)&axr[12] = *(const float4*)&axs[mr * 16 + 12];
      float* orow = out + (size_t)(m0 + mr) * N_DIM + n0;
#pragma unroll
      for (int ni = 0; ni < 4; ni++) {
        const int c = cbase + ni * 8;
        const float* b0 = &bs[c * 17];
        const float* b1 = &bs[(c + 1) * 17];
        float l0 = 0.f, l1 = 0.f;
#pragma unroll
        for (int r = 0; r < 16; r++) {
          l0 += axr[r] * b0[r];
          l1 += axr[r] * b1[r];
        }
        float2 v = make_float2(acc[mi][ni][half * 2 + 0] + l0,
                               acc[mi][ni][half * 2 + 1] + l1);
        *(float2*)&orow[c] = v;
      }
    }
  }
}

// ---------------------------------------------------------------------------
extern "C" void kernel_launch(void* const* d_in, const int* in_sizes, int n_in,
                              void* d_out, int out_size) {
  const float* x = (const float*)d_in[0];
  const int* codes = (const int*)d_in[1];
  const float* absmax = (const float*)d_in[2];
  const float* A = (const float*)d_in[3];
  const float* Bw = (const float*)d_in[4];
  float* out = (float*)d_out;

  cudaFuncSetAttribute(qlora_mma_kernel,
                       cudaFuncAttributeMaxDynamicSharedMemorySize, SMEMB);

  split_x_kernel<<<(M_DIM * (size_t)K_DIM) / 1024, 256>>>(x);
  dequant_split_kernel<<<(N_DIM * (size_t)K_DIM) / 1024, 256>>>(codes, absmax);
  lora_ax_kernel<<<M_DIM / 32, 256>>>(x, A);

  dim3 grid(N_DIM / TN, M_DIM / TM);
  qlora_mma_kernel<<<grid, 256, SMEMB>>>(Bw, out);
}

// round 4
// speedup vs baseline: 2.6089x; 1.1378x over previous
#include <cuda_runtime.h>
#include <cuda_bf16.h>
#include <cstdint>

// QLoRA linear via legacy mma.sync (HMMA) 3xBF16-split GEMM.
// out = x @ dequant_nf4(w)^T + 2.0 * (x @ A^T) @ B^T

#define M_DIM 8192
#define N_DIM 4096
#define K_DIM 4096
#define R_DIM 16
#define TM 128
#define TN 128
#define BK 32
#define NK (K_DIM / BK)   // 128

#define TILEB 8192            // 128 rows x 64B (swizzled, no pad)
#define STAGEB (4 * TILEB)    // Ahi, Alo, Bhi, Blo = 32768
#define NSTG 3
#define SMEMB (NSTG * STAGEB) // 98304

// ---- device scratch ----
__device__ float g_ax[M_DIM * R_DIM];
__device__ __nv_bfloat16 g_xhi[(size_t)M_DIM * K_DIM];
__device__ __nv_bfloat16 g_xlo[(size_t)M_DIM * K_DIM];
__device__ __nv_bfloat16 g_whi[(size_t)N_DIM * K_DIM];
__device__ __nv_bfloat16 g_wlo[(size_t)N_DIM * K_DIM];

__constant__ float c_nf4[16] = {
    -1.0f, -0.6961928009986877f, -0.5250730514526367f, -0.39491748809814453f,
    -0.28444138169288635f, -0.18477343022823334f, -0.09105003625154495f, 0.0f,
    0.07958029955625534f, 0.16093020141124725f, 0.24611230194568634f,
    0.33791524171829224f, 0.44070982933044434f, 0.5626170039176941f,
    0.7229568362236023f, 1.0f};

// ---------------------------------------------------------------------------
__device__ __forceinline__ uint32_t smem_u32(const void* p) {
  return (uint32_t)__cvta_generic_to_shared((void*)p);
}
__device__ __forceinline__ uint32_t swz(uint32_t off) {
  return off ^ (((off >> 7) & 7u) << 4);
}
__device__ __forceinline__ void cpa16(uint32_t s, const void* g) {
  asm volatile("cp.async.cg.shared.global [%0], [%1], 16;" :: "r"(s), "l"(g));
}
__device__ __forceinline__ void ldsm4(uint32_t (&r)[4], uint32_t addr) {
  asm volatile(
      "ldmatrix.sync.aligned.m8n8.x4.shared.b16 {%0,%1,%2,%3}, [%4];"
      : "=r"(r[0]), "=r"(r[1]), "=r"(r[2]), "=r"(r[3]) : "r"(addr));
}
__device__ __forceinline__ void mma_bf16(float (&d)[4], const uint32_t (&a)[4],
                                         uint32_t b0, uint32_t b1) {
  asm volatile(
      "mma.sync.aligned.m16n8k16.row.col.f32.bf16.bf16.f32 "
      "{%0,%1,%2,%3}, {%4,%5,%6,%7}, {%8,%9}, {%0,%1,%2,%3};"
      : "+f"(d[0]), "+f"(d[1]), "+f"(d[2]), "+f"(d[3])
      : "r"(a[0]), "r"(a[1]), "r"(a[2]), "r"(a[3]), "r"(b0), "r"(b1));
}

// ---------------------------------------------------------------------------
// Precompute kernels
// ---------------------------------------------------------------------------
__global__ __launch_bounds__(256) void split_x_kernel(
    const float* __restrict__ x) {
  size_t i4 = (size_t)blockIdx.x * 256 + threadIdx.x;
  float4 v = ((const float4*)x)[i4];
  float vv[4] = {v.x, v.y, v.z, v.w};
  __nv_bfloat16 h[4], l[4];
#pragma unroll
  for (int e = 0; e < 4; e++) {
    h[e] = __float2bfloat16_rn(vv[e]);
    l[e] = __float2bfloat16_rn(vv[e] - __bfloat162float(h[e]));
  }
  *(uint2*)&g_xhi[i4 * 4] = *(uint2*)h;
  *(uint2*)&g_xlo[i4 * 4] = *(uint2*)l;
}

__global__ __launch_bounds__(256) void dequant_split_kernel(
    const int* __restrict__ codes, const float* __restrict__ absmax) {
  __shared__ float lut[16];
  if (threadIdx.x < 16) lut[threadIdx.x] = c_nf4[threadIdx.x];
  __syncthreads();
  size_t i4 = (size_t)blockIdx.x * 256 + threadIdx.x;
  int4 c = ((const int4*)codes)[i4];
  size_t e0 = i4 * 4;
  int row = (int)(e0 >> 12);
  int col = (int)(e0 & 4095);
  float am = absmax[row * (K_DIM / 64) + (col >> 6)];
  float w[4] = {lut[c.x] * am, lut[c.y] * am, lut[c.z] * am, lut[c.w] * am};
  __nv_bfloat16 h[4], l[4];
#pragma unroll
  for (int e = 0; e < 4; e++) {
    h[e] = __float2bfloat16_rn(w[e]);
    l[e] = __float2bfloat16_rn(w[e] - __bfloat162float(h[e]));
  }
  *(uint2*)&g_whi[e0] = *(uint2*)h;
  *(uint2*)&g_wlo[e0] = *(uint2*)l;
}

__global__ __launch_bounds__(256) void lora_ax_kernel(
    const float* __restrict__ x, const float* __restrict__ A) {
  __shared__ float Xc[32][65];
  __shared__ float Ac[64][16];
  const int tid = threadIdx.x;
  const int m0 = blockIdx.x * 32;
  const int r = tid & 15;
  const int ml = tid >> 4;
  float acc0 = 0.f, acc1 = 0.f;
  for (int kc = 0; kc < K_DIM; kc += 64) {
#pragma unroll
    for (int i = 0; i < 8; i++) {
      int idx = tid + i * 256;
      Xc[idx >> 6][idx & 63] =
          x[(size_t)(m0 + (idx >> 6)) * K_DIM + kc + (idx & 63)];
    }
#pragma unroll
    for (int i = 0; i < 4; i++) {
      int idx = tid + i * 256;
      Ac[idx >> 4][idx & 15] = A[(idx & 15) * K_DIM + kc + (idx >> 4)];
    }
    __syncthreads();
#pragma unroll 8
    for (int kk = 0; kk < 64; kk++) {
      float av = Ac[kk][r];
      acc0 += Xc[ml][kk] * av;
      acc1 += Xc[ml + 16][kk] * av;
    }
    __syncthreads();
  }
  g_ax[(size_t)(m0 + ml) * R_DIM + r] = acc0 * 2.0f;
  g_ax[(size_t)(m0 + ml + 16) * R_DIM + r] = acc1 * 2.0f;
}

// ---------------------------------------------------------------------------
// Main HMMA GEMM: 128x128 tile, BK=32, 3-stage cp.async pipeline, swizzled smem
// ---------------------------------------------------------------------------
__global__ __launch_bounds__(256, 2) void qlora_mma_kernel(
    const float* __restrict__ Bw, float* __restrict__ out) {
  extern __shared__ char sm[];
  const int tid = threadIdx.x;
  const int wid = tid >> 5;
  const int lane = tid & 31;
  const int n0 = blockIdx.x * TN;
  const int m0 = blockIdx.y * TM;
  const int warp_m0 = (wid >> 2) * 64;
  const int warp_n0 = (wid & 3) * 32;
  const uint32_t sbase = smem_u32(sm);

  const __nv_bfloat16* Ah = g_xhi + (size_t)m0 * K_DIM;
  const __nv_bfloat16* Al = g_xlo + (size_t)m0 * K_DIM;
  const __nv_bfloat16* Bh = g_whi + (size_t)n0 * K_DIM;
  const __nv_bfloat16* Bl = g_wlo + (size_t)n0 * K_DIM;

  // loader per-thread offsets (2 chunks of 16B per tile per stage)
  const int cid0 = tid;          // chunk 0..255
  const int cid1 = tid + 256;    // chunk 256..511
  const int lr0 = cid0 >> 2, lc0 = cid0 & 3;
  const int lr1 = cid1 >> 2, lc1 = cid1 & 3;
  const size_t go0 = (size_t)lr0 * K_DIM + lc0 * 8;
  const size_t go1 = (size_t)lr1 * K_DIM + lc1 * 8;
  const uint32_t so0 = swz((lr0 >> 1) * 128 + (lr0 & 1) * 64 + lc0 * 16);
  const uint32_t so1 = swz((lr1 >> 1) * 128 + (lr1 & 1) * 64 + lc1 * 16);

#define LOAD_STAGE(SB, KT)                                                     \
  do {                                                                         \
    uint32_t _sb = (SB);                                                       \
    int _kt = (KT);                                                            \
    cpa16(_sb + so0, Ah + go0 + _kt);                                          \
    cpa16(_sb + TILEB + so0, Al + go0 + _kt);                                  \
    cpa16(_sb + 2 * TILEB + so0, Bh + go0 + _kt);                              \
    cpa16(_sb + 3 * TILEB + so0, Bl + go0 + _kt);                              \
    cpa16(_sb + so1, Ah + go1 + _kt);                                          \
    cpa16(_sb + TILEB + so1, Al + go1 + _kt);                                  \
    cpa16(_sb + 2 * TILEB + so1, Bh + go1 + _kt);                              \
    cpa16(_sb + 3 * TILEB + so1, Bl + go1 + _kt);                              \
  } while (0)

  // fragment offsets (swizzled, relative to stage base / hi tiles)
  const int rl = lane & 15;
  const int chalf = (lane >> 4) * 16;
  uint32_t offA[2][4], offB[2][2];
#pragma unroll
  for (int ks = 0; ks < 2; ks++) {
#pragma unroll
    for (int mi = 0; mi < 4; mi++) {
      int row = warp_m0 + mi * 16 + rl;
      offA[ks][mi] =
          swz((row >> 1) * 128 + (row & 1) * 64 + ks * 32 + chalf);
    }
#pragma unroll
    for (int np = 0; np < 2; np++) {
      int row = warp_n0 + np * 16 + rl;
      offB[ks][np] = 2 * TILEB +
          swz((row >> 1) * 128 + (row & 1) * 64 + ks * 32 + chalf);
    }
  }

  float acc[4][4][4];
#pragma unroll
  for (int i = 0; i < 4; i++)
#pragma unroll
    for (int j = 0; j < 4; j++)
#pragma unroll
      for (int e = 0; e < 4; e++) acc[i][j][e] = 0.f;

  // prologue: stages 0,1
  LOAD_STAGE(sbase, 0);
  asm volatile("cp.async.commit_group;" ::: "memory");
  LOAD_STAGE(sbase + STAGEB, BK);
  asm volatile("cp.async.commit_group;" ::: "memory");

  int slot = 0, wslot = 2;
  for (int k = 0; k < NK; k++) {
    asm volatile("cp.async.wait_group 1;" ::: "memory");
    __syncthreads();

    // issue next load before compute (slot freed by compute k-1)
    if (k + 2 < NK) LOAD_STAGE(sbase + wslot * STAGEB, (k + 2) * BK);
    asm volatile("cp.async.commit_group;" ::: "memory");

    const uint32_t sb = sbase + slot * STAGEB;
#pragma unroll
    for (int ks = 0; ks < 2; ks++) {
      uint32_t bh[2][4], bl[2][4], af[4][4];
      ldsm4(bh[0], sb + offB[ks][0]);
      ldsm4(bh[1], sb + offB[ks][1]);
      ldsm4(bl[0], sb + TILEB + offB[ks][0]);
      ldsm4(bl[1], sb + TILEB + offB[ks][1]);
#pragma unroll
      for (int mi = 0; mi < 4; mi++) ldsm4(af[mi], sb + offA[ks][mi]);
#pragma unroll
      for (int mi = 0; mi < 4; mi++)
#pragma unroll
        for (int ni = 0; ni < 4; ni++) {
          mma_bf16(acc[mi][ni], af[mi], bh[ni >> 1][ni & 1],
                   bh[ni >> 1][2 + (ni & 1)]);
          mma_bf16(acc[mi][ni], af[mi], bl[ni >> 1][ni & 1],
                   bl[ni >> 1][2 + (ni & 1)]);
        }
#pragma unroll
      for (int mi = 0; mi < 4; mi++)
        ldsm4(af[mi], sb + TILEB + offA[ks][mi]);
#pragma unroll
      for (int mi = 0; mi < 4; mi++)
#pragma unroll
        for (int ni = 0; ni < 4; ni++)
          mma_bf16(acc[mi][ni], af[mi], bh[ni >> 1][ni & 1],
                   bh[ni >> 1][2 + (ni & 1)]);
    }

    slot = (slot == 2) ? 0 : slot + 1;
    wslot = (wslot == 2) ? 0 : wslot + 1;
  }

  // ---- epilogue: LoRA + store ----
  asm volatile("cp.async.wait_all;" ::: "memory");
  __syncthreads();

  float* axs = (float*)sm;                    // [128][16]
  float* bs = (float*)(sm + 128 * 16 * 4);    // [128] stride 17
  for (int j = tid; j < TM * R_DIM; j += 256)
    axs[j] = g_ax[(size_t)m0 * R_DIM + j];
  for (int j = tid; j < TN * R_DIM; j += 256) {
    int col = j >> 4, r = j & 15;
    bs[col * 17 + r] = Bw[(size_t)(n0 + col) * R_DIM + r];
  }
  __syncthreads();

  const int r0 = lane >> 2;
  const int cbase = warp_n0 + (lane & 3) * 2;
#pragma unroll
  for (int mi = 0; mi < 4; mi++) {
#pragma unroll
    for (int half = 0; half < 2; half++) {
      const int mr = warp_m0 + mi * 16 + r0 + half * 8;
      float axr[16];
      *(float4*)&axr[0] = *(const float4*)&axs[mr * 16];
      *(float4*)&axr[4] = *(const float4*)&axs[mr * 16 + 4];
      *(float4*)&axr[8] = *(const float4*)&axs[mr * 16 + 8];
      *(float4*)&axr[12] = *(const float4*)&axs[mr * 16 + 12];
      float* orow = out + (size_t)(m0 + mr) * N_DIM + n0;
#pragma unroll
      for (int ni = 0; ni < 4; ni++) {
        const int c = cbase + ni * 8;
        const float* b0 = &bs[c * 17];
        const float* b1 = &bs[(c + 1) * 17];
        float l0 = 0.f, l1 = 0.f;
#pragma unroll
        for (int r = 0; r < 16; r++) {
          l0 += axr[r] * b0[r];
          l1 += axr[r] * b1[r];
        }
        float2 v = make_float2(acc[mi][ni][half * 2 + 0] + l0,
                               acc[mi][ni][half * 2 + 1] + l1);
        *(float2*)&orow[c] = v;
      }
    }
  }
}

// ---------------------------------------------------------------------------
extern "C" void kernel_launch(void* const* d_in, const int* in_sizes, int n_in,
                              void* d_out, int out_size) {
  const float* x = (const float*)d_in[0];
  const int* codes = (const int*)d_in[1];
  const float* absmax = (const float*)d_in[2];
  const float* A = (const float*)d_in[3];
  const float* Bw = (const float*)d_in[4];
  float* out = (float*)d_out;

  cudaFuncSetAttribute(qlora_mma_kernel,
                       cudaFuncAttributeMaxDynamicSharedMemorySize, SMEMB);

  split_x_kernel<<<(M_DIM * (size_t)K_DIM) / 1024, 256>>>(x);
  dequant_split_kernel<<<(N_DIM * (size_t)K_DIM) / 1024, 256>>>(codes, absmax);
  lora_ax_kernel<<<M_DIM / 32, 256>>>(x, A);

  dim3 grid(N_DIM / TN, M_DIM / TM);
  qlora_mma_kernel<<<grid, 256, SMEMB>>>(Bw, out);
}

// round 5
// speedup vs baseline: 3.7641x; 1.4428x over previous
#include <cuda_runtime.h>
#include <cuda_fp16.h>
#include <cstdint>

// QLoRA linear via mma.sync fp16 2-term GEMM:
// x*w ~= fp16(x)*wh + fp16(x)*wl, w = wh + wl (fp16 pair, exact to 2^-24).
// out = x @ dequant_nf4(w)^T + 2.0 * (x @ A^T) @ B^T

#define M_DIM 8192
#define N_DIM 4096
#define K_DIM 4096
#define R_DIM 16
#define TM 128
#define TN 128
#define BK 32
#define NK (K_DIM / BK)   // 128

#define TILEB 8192            // 128 rows x 64B (swizzled, no pad)
#define STAGEB (3 * TILEB)    // X, Wh, Wl = 24576
#define NSTG 4
#define SMEMB (NSTG * STAGEB) // 98304

// ---- device scratch ----
__device__ float g_ax[M_DIM * R_DIM];
__device__ __half g_xh[(size_t)M_DIM * K_DIM];
__device__ __half g_wh[(size_t)N_DIM * K_DIM];
__device__ __half g_wl[(size_t)N_DIM * K_DIM];

__constant__ float c_nf4[16] = {
    -1.0f, -0.6961928009986877f, -0.5250730514526367f, -0.39491748809814453f,
    -0.28444138169288635f, -0.18477343022823334f, -0.09105003625154495f, 0.0f,
    0.07958029955625534f, 0.16093020141124725f, 0.24611230194568634f,
    0.33791524171829224f, 0.44070982933044434f, 0.5626170039176941f,
    0.7229568362236023f, 1.0f};

// ---------------------------------------------------------------------------
__device__ __forceinline__ uint32_t smem_u32(const void* p) {
  return (uint32_t)__cvta_generic_to_shared((void*)p);
}
__device__ __forceinline__ uint32_t swz(uint32_t off) {
  return off ^ (((off >> 7) & 7u) << 4);
}
__device__ __forceinline__ void cpa16(uint32_t s, const void* g) {
  asm volatile("cp.async.cg.shared.global [%0], [%1], 16;" :: "r"(s), "l"(g));
}
__device__ __forceinline__ void ldsm4(uint32_t (&r)[4], uint32_t addr) {
  asm volatile(
      "ldmatrix.sync.aligned.m8n8.x4.shared.b16 {%0,%1,%2,%3}, [%4];"
      : "=r"(r[0]), "=r"(r[1]), "=r"(r[2]), "=r"(r[3]) : "r"(addr));
}
__device__ __forceinline__ void mma_f16(float (&d)[4], const uint32_t (&a)[4],
                                        uint32_t b0, uint32_t b1) {
  asm volatile(
      "mma.sync.aligned.m16n8k16.row.col.f32.f16.f16.f32 "
      "{%0,%1,%2,%3}, {%4,%5,%6,%7}, {%8,%9}, {%0,%1,%2,%3};"
      : "+f"(d[0]), "+f"(d[1]), "+f"(d[2]), "+f"(d[3])
      : "r"(a[0]), "r"(a[1]), "r"(a[2]), "r"(a[3]), "r"(b0), "r"(b1));
}

// ---------------------------------------------------------------------------
// Precompute kernels
// ---------------------------------------------------------------------------
__global__ __launch_bounds__(256) void split_x_kernel(
    const float* __restrict__ x) {
  size_t i4 = (size_t)blockIdx.x * 256 + threadIdx.x;
  float4 v = ((const float4*)x)[i4];
  __half h[4] = {__float2half_rn(v.x), __float2half_rn(v.y),
                 __float2half_rn(v.z), __float2half_rn(v.w)};
  *(uint2*)&g_xh[i4 * 4] = *(uint2*)h;
}

__global__ __launch_bounds__(256) void dequant_split_kernel(
    const int* __restrict__ codes, const float* __restrict__ absmax) {
  __shared__ float lut[16];
  if (threadIdx.x < 16) lut[threadIdx.x] = c_nf4[threadIdx.x];
  __syncthreads();
  size_t i4 = (size_t)blockIdx.x * 256 + threadIdx.x;
  int4 c = ((const int4*)codes)[i4];
  size_t e0 = i4 * 4;
  int row = (int)(e0 >> 12);
  int col = (int)(e0 & 4095);
  float am = absmax[row * (K_DIM / 64) + (col >> 6)];
  float w[4] = {lut[c.x] * am, lut[c.y] * am, lut[c.z] * am, lut[c.w] * am};
  __half h[4], l[4];
#pragma unroll
  for (int e = 0; e < 4; e++) {
    h[e] = __float2half_rn(w[e]);
    l[e] = __float2half_rn(w[e] - __half2float(h[e]));
  }
  *(uint2*)&g_wh[e0] = *(uint2*)h;
  *(uint2*)&g_wl[e0] = *(uint2*)l;
}

__global__ __launch_bounds__(256) void lora_ax_kernel(
    const float* __restrict__ x, const float* __restrict__ A) {
  __shared__ float Xc[32][65];
  __shared__ float Ac[64][16];
  const int tid = threadIdx.x;
  const int m0 = blockIdx.x * 32;
  const int r = tid & 15;
  const int ml = tid >> 4;
  float acc0 = 0.f, acc1 = 0.f;
  for (int kc = 0; kc < K_DIM; kc += 64) {
#pragma unroll
    for (int i = 0; i < 8; i++) {
      int idx = tid + i * 256;
      Xc[idx >> 6][idx & 63] =
          x[(size_t)(m0 + (idx >> 6)) * K_DIM + kc + (idx & 63)];
    }
#pragma unroll
    for (int i = 0; i < 4; i++) {
      int idx = tid + i * 256;
      Ac[idx >> 4][idx & 15] = A[(idx & 15) * K_DIM + kc + (idx >> 4)];
    }
    __syncthreads();
#pragma unroll 8
    for (int kk = 0; kk < 64; kk++) {
      float av = Ac[kk][r];
      acc0 += Xc[ml][kk] * av;
      acc1 += Xc[ml + 16][kk] * av;
    }
    __syncthreads();
  }
  g_ax[(size_t)(m0 + ml) * R_DIM + r] = acc0 * 2.0f;
  g_ax[(size_t)(m0 + ml + 16) * R_DIM + r] = acc1 * 2.0f;
}

// ---------------------------------------------------------------------------
// Main HMMA GEMM: 128x128 tile, BK=32, 4-stage cp.async pipeline, swizzled smem
// ---------------------------------------------------------------------------
__global__ __launch_bounds__(256, 2) void qlora_mma_kernel(
    const float* __restrict__ Bw, float* __restrict__ out) {
  extern __shared__ char sm[];
  const int tid = threadIdx.x;
  const int wid = tid >> 5;
  const int lane = tid & 31;
  const int n0 = blockIdx.x * TN;
  const int m0 = blockIdx.y * TM;
  const int warp_m0 = (wid >> 2) * 64;
  const int warp_n0 = (wid & 3) * 32;
  const uint32_t sbase = smem_u32(sm);

  const __half* Xh = g_xh + (size_t)m0 * K_DIM;
  const __half* Wh = g_wh + (size_t)n0 * K_DIM;
  const __half* Wl = g_wl + (size_t)n0 * K_DIM;

  // loader per-thread offsets (2 chunks of 16B per tile per stage)
  const int cid0 = tid;
  const int cid1 = tid + 256;
  const int lr0 = cid0 >> 2, lc0 = cid0 & 3;
  const int lr1 = cid1 >> 2, lc1 = cid1 & 3;
  const size_t go0 = (size_t)lr0 * K_DIM + lc0 * 8;
  const size_t go1 = (size_t)lr1 * K_DIM + lc1 * 8;
  const uint32_t so0 = swz((lr0 >> 1) * 128 + (lr0 & 1) * 64 + lc0 * 16);
  const uint32_t so1 = swz((lr1 >> 1) * 128 + (lr1 & 1) * 64 + lc1 * 16);

#define LOAD_STAGE(SB, KT)                                                     \
  do {                                                                         \
    uint32_t _sb = (SB);                                                       \
    int _kt = (KT);                                                            \
    cpa16(_sb + so0, Xh + go0 + _kt);                                          \
    cpa16(_sb + TILEB + so0, Wh + go0 + _kt);                                  \
    cpa16(_sb + 2 * TILEB + so0, Wl + go0 + _kt);                              \
    cpa16(_sb + so1, Xh + go1 + _kt);                                          \
    cpa16(_sb + TILEB + so1, Wh + go1 + _kt);                                  \
    cpa16(_sb + 2 * TILEB + so1, Wl + go1 + _kt);                              \
  } while (0)

  // fragment smem offsets (swizzled, relative to stage base)
  const int rl = lane & 15;
  const int chalf = (lane >> 4) * 16;
  uint32_t offA[2][4], offB[2][2];
#pragma unroll
  for (int ks = 0; ks < 2; ks++) {
#pragma unroll
    for (int mi = 0; mi < 4; mi++) {
      int row = warp_m0 + mi * 16 + rl;
      offA[ks][mi] = swz((row >> 1) * 128 + (row & 1) * 64 + ks * 32 + chalf);
    }
#pragma unroll
    for (int np = 0; np < 2; np++) {
      int row = warp_n0 + np * 16 + rl;
      offB[ks][np] = swz((row >> 1) * 128 + (row & 1) * 64 + ks * 32 + chalf);
    }
  }

  float acc[4][4][4];
#pragma unroll
  for (int i = 0; i < 4; i++)
#pragma unroll
    for (int j = 0; j < 4; j++)
#pragma unroll
      for (int e = 0; e < 4; e++) acc[i][j][e] = 0.f;

  // prologue: stages 0..2
  LOAD_STAGE(sbase, 0);
  asm volatile("cp.async.commit_group;" ::: "memory");
  LOAD_STAGE(sbase + STAGEB, BK);
  asm volatile("cp.async.commit_group;" ::: "memory");
  LOAD_STAGE(sbase + 2 * STAGEB, 2 * BK);
  asm volatile("cp.async.commit_group;" ::: "memory");

  for (int k = 0; k < NK; k++) {
    asm volatile("cp.async.wait_group 2;" ::: "memory");
    __syncthreads();

    if (k + 3 < NK) LOAD_STAGE(sbase + ((k + 3) & 3) * STAGEB, (k + 3) * BK);
    asm volatile("cp.async.commit_group;" ::: "memory");

    const uint32_t sb = sbase + (k & 3) * STAGEB;
#pragma unroll
    for (int ks = 0; ks < 2; ks++) {
      uint32_t bh[2][4], bl[2][4], af[4][4];
      ldsm4(bh[0], sb + TILEB + offB[ks][0]);
      ldsm4(bh[1], sb + TILEB + offB[ks][1]);
      ldsm4(bl[0], sb + 2 * TILEB + offB[ks][0]);
      ldsm4(bl[1], sb + 2 * TILEB + offB[ks][1]);
#pragma unroll
      for (int mi = 0; mi < 4; mi++) ldsm4(af[mi], sb + offA[ks][mi]);
#pragma unroll
      for (int mi = 0; mi < 4; mi++)
#pragma unroll
        for (int ni = 0; ni < 4; ni++) {
          mma_f16(acc[mi][ni], af[mi], bh[ni >> 1][ni & 1],
                  bh[ni >> 1][2 + (ni & 1)]);
          mma_f16(acc[mi][ni], af[mi], bl[ni >> 1][ni & 1],
                  bl[ni >> 1][2 + (ni & 1)]);
        }
    }
  }

  // ---- epilogue: LoRA + store ----
  asm volatile("cp.async.wait_all;" ::: "memory");
  __syncthreads();

  float* axs = (float*)sm;                    // [128][16]
  float* bs = (float*)(sm + 128 * 16 * 4);    // [128] stride 17
  for (int j = tid; j < TM * R_DIM; j += 256)
    axs[j] = g_ax[(size_t)m0 * R_DIM + j];
  for (int j = tid; j < TN * R_DIM; j += 256) {
    int col = j >> 4, r = j & 15;
    bs[col * 17 + r] = Bw[(size_t)(n0 + col) * R_DIM + r];
  }
  __syncthreads();

  const int r0 = lane >> 2;
  const int cbase = warp_n0 + (lane & 3) * 2;
#pragma unroll
  for (int mi = 0; mi < 4; mi++) {
#pragma unroll
    for (int half = 0; half < 2; half++) {
      const int mr = warp_m0 + mi * 16 + r0 + half * 8;
      float axr[16];
      *(float4*)&axr[0] = *(const float4*)&axs[mr * 16];
      *(float4*)&axr[4] = *(const float4*)&axs[mr * 16 + 4];
      *(float4*)&axr[8] = *(const float4*)&axs[mr * 16 + 8];
      *(float4*)&axr[12] = *(const float4*)&axs[mr * 16 + 12];
      float* orow = out + (size_t)(m0 + mr) * N_DIM + n0;
#pragma unroll
      for (int ni = 0; ni < 4; ni++) {
        const int c = cbase + ni * 8;
        const float* b0 = &bs[c * 17];
        const float* b1 = &bs[(c + 1) * 17];
        float l0 = 0.f, l1 = 0.f;
#pragma unroll
        for (int r = 0; r < 16; r++) {
          l0 += axr[r] * b0[r];
          l1 += axr[r] * b1[r];
        }
        float2 v = make_float2(acc[mi][ni][half * 2 + 0] + l0,
                               acc[mi][ni][half * 2 + 1] + l1);
        *(float2*)&orow[c] = v;
      }
    }
  }
}

// ---------------------------------------------------------------------------
extern "C" void kernel_launch(void* const* d_in, const int* in_sizes, int n_in,
                              void* d_out, int out_size) {
  const float* x = (const float*)d_in[0];
  const int* codes = (const int*)d_in[1];
  const float* absmax = (const float*)d_in[2];
  const float* A = (const float*)d_in[3];
  const float* Bw = (const float*)d_in[4];
  float* out = (float*)d_out;

  cudaFuncSetAttribute(qlora_mma_kernel,
                       cudaFuncAttributeMaxDynamicSharedMemorySize, SMEMB);

  split_x_kernel<<<(M_DIM * (size_t)K_DIM) / 1024, 256>>>(x);
  dequant_split_kernel<<<(N_DIM * (size_t)K_DIM) / 1024, 256>>>(codes, absmax);
  lora_ax_kernel<<<M_DIM / 32, 256>>>(x, A);

  dim3 grid(N_DIM / TN, M_DIM / TM);
  qlora_mma_kernel<<<grid, 256, SMEMB>>>(Bw, out);
}

// round 6
// speedup vs baseline: 4.1544x; 1.1037x over previous
#include <cuda_runtime.h>
#include <cuda_fp16.h>
#include <cstdint>

// QLoRA linear via mma.sync fp16 single-term GEMM:
// out = fp16(x) @ fp16(dequant_nf4(w))^T  (fp32 accum)  + 2.0*(x@A^T)@B^T
// Error: x-rounding (2^-11) + w-rounding (2^-11), combined ~3e-4 l2-rel.

#define M_DIM 8192
#define N_DIM 4096
#define K_DIM 4096
#define R_DIM 16
#define TM 128
#define TN 128
#define BK 64
#define NK (K_DIM / BK)   // 64

#define TILEB 16384           // 128 rows x 128B (swizzled, SW128)
#define STAGEB (2 * TILEB)    // X, W = 32768
#define NSTG 3
#define SMEMB (NSTG * STAGEB) // 98304

// ---- device scratch ----
__device__ float g_ax[M_DIM * R_DIM];
__device__ __half g_xh[(size_t)M_DIM * K_DIM];
__device__ __half g_wh[(size_t)N_DIM * K_DIM];

__constant__ float c_nf4[16] = {
    -1.0f, -0.6961928009986877f, -0.5250730514526367f, -0.39491748809814453f,
    -0.28444138169288635f, -0.18477343022823334f, -0.09105003625154495f, 0.0f,
    0.07958029955625534f, 0.16093020141124725f, 0.24611230194568634f,
    0.33791524171829224f, 0.44070982933044434f, 0.5626170039176941f,
    0.7229568362236023f, 1.0f};

// ---------------------------------------------------------------------------
__device__ __forceinline__ uint32_t smem_u32(const void* p) {
  return (uint32_t)__cvta_generic_to_shared((void*)p);
}
// SW128 swizzle for 128B rows: XOR bits[6:4] of col with row&7
__device__ __forceinline__ uint32_t swz(uint32_t off) {
  return off ^ (((off >> 7) & 7u) << 4);
}
__device__ __forceinline__ void cpa16(uint32_t s, const void* g) {
  asm volatile("cp.async.cg.shared.global [%0], [%1], 16;" :: "r"(s), "l"(g));
}
__device__ __forceinline__ void ldsm4(uint32_t (&r)[4], uint32_t addr) {
  asm volatile(
      "ldmatrix.sync.aligned.m8n8.x4.shared.b16 {%0,%1,%2,%3}, [%4];"
      : "=r"(r[0]), "=r"(r[1]), "=r"(r[2]), "=r"(r[3]) : "r"(addr));
}
__device__ __forceinline__ void mma_f16(float (&d)[4], const uint32_t (&a)[4],
                                        uint32_t b0, uint32_t b1) {
  asm volatile(
      "mma.sync.aligned.m16n8k16.row.col.f32.f16.f16.f32 "
      "{%0,%1,%2,%3}, {%4,%5,%6,%7}, {%8,%9}, {%0,%1,%2,%3};"
      : "+f"(d[0]), "+f"(d[1]), "+f"(d[2]), "+f"(d[3])
      : "r"(a[0]), "r"(a[1]), "r"(a[2]), "r"(a[3]), "r"(b0), "r"(b1));
}

// ---------------------------------------------------------------------------
// Precompute kernels
// ---------------------------------------------------------------------------
__global__ __launch_bounds__(256) void split_x_kernel(
    const float* __restrict__ x) {
  size_t i4 = (size_t)blockIdx.x * 256 + threadIdx.x;
  float4 v = ((const float4*)x)[i4];
  __half h[4] = {__float2half_rn(v.x), __float2half_rn(v.y),
                 __float2half_rn(v.z), __float2half_rn(v.w)};
  *(uint2*)&g_xh[i4 * 4] = *(uint2*)h;
}

__global__ __launch_bounds__(256) void dequant_kernel(
    const int* __restrict__ codes, const float* __restrict__ absmax) {
  __shared__ float lut[16];
  if (threadIdx.x < 16) lut[threadIdx.x] = c_nf4[threadIdx.x];
  __syncthreads();
  size_t i4 = (size_t)blockIdx.x * 256 + threadIdx.x;
  int4 c = ((const int4*)codes)[i4];
  size_t e0 = i4 * 4;
  int row = (int)(e0 >> 12);
  int col = (int)(e0 & 4095);
  float am = absmax[row * (K_DIM / 64) + (col >> 6)];
  __half h[4] = {__float2half_rn(lut[c.x] * am), __float2half_rn(lut[c.y] * am),
                 __float2half_rn(lut[c.z] * am), __float2half_rn(lut[c.w] * am)};
  *(uint2*)&g_wh[e0] = *(uint2*)h;
}

__global__ __launch_bounds__(256) void lora_ax_kernel(
    const float* __restrict__ x, const float* __restrict__ A) {
  __shared__ float Xc[32][65];
  __shared__ float Ac[64][16];
  const int tid = threadIdx.x;
  const int m0 = blockIdx.x * 32;
  const int r = tid & 15;
  const int ml = tid >> 4;
  float acc0 = 0.f, acc1 = 0.f;
  for (int kc = 0; kc < K_DIM; kc += 64) {
#pragma unroll
    for (int i = 0; i < 8; i++) {
      int idx = tid + i * 256;
      Xc[idx >> 6][idx & 63] =
          x[(size_t)(m0 + (idx >> 6)) * K_DIM + kc + (idx & 63)];
    }
#pragma unroll
    for (int i = 0; i < 4; i++) {
      int idx = tid + i * 256;
      Ac[idx >> 4][idx & 15] = A[(idx & 15) * K_DIM + kc + (idx >> 4)];
    }
    __syncthreads();
#pragma unroll 8
    for (int kk = 0; kk < 64; kk++) {
      float av = Ac[kk][r];
      acc0 += Xc[ml][kk] * av;
      acc1 += Xc[ml + 16][kk] * av;
    }
    __syncthreads();
  }
  g_ax[(size_t)(m0 + ml) * R_DIM + r] = acc0 * 2.0f;
  g_ax[(size_t)(m0 + ml + 16) * R_DIM + r] = acc1 * 2.0f;
}

// ---------------------------------------------------------------------------
// Main HMMA GEMM: 128x128 tile, BK=64, 3-stage cp.async pipeline, SW128 smem
// ---------------------------------------------------------------------------
__global__ __launch_bounds__(256, 2) void qlora_mma_kernel(
    const float* __restrict__ Bw, float* __restrict__ out) {
  extern __shared__ char sm[];
  const int tid = threadIdx.x;
  const int wid = tid >> 5;
  const int lane = tid & 31;
  const int n0 = blockIdx.x * TN;
  const int m0 = blockIdx.y * TM;
  const int warp_m0 = (wid >> 2) * 64;
  const int warp_n0 = (wid & 3) * 32;
  const uint32_t sbase = smem_u32(sm);

  const __half* Xh = g_xh + (size_t)m0 * K_DIM;
  const __half* Wh = g_wh + (size_t)n0 * K_DIM;

  // loader: 4 chunks of 16B per tile per stage (tile = 128 rows x 128B)
  // chunk c: row = c>>3, colchunk = c&7; coalesced 128B per 8 threads.
  uint32_t so[4];
  size_t go[4];
#pragma unroll
  for (int j = 0; j < 4; j++) {
    int c = tid + j * 256;
    int row = c >> 3, cc = c & 7;
    go[j] = (size_t)row * K_DIM + cc * 8;
    so[j] = swz((uint32_t)(row * 128 + cc * 16));
  }

#define LOAD_STAGE(SB, KT)                                                     \
  do {                                                                         \
    uint32_t _sb = (SB);                                                       \
    int _kt = (KT);                                                            \
    cpa16(_sb + so[0], Xh + go[0] + _kt);                                      \
    cpa16(_sb + so[1], Xh + go[1] + _kt);                                      \
    cpa16(_sb + so[2], Xh + go[2] + _kt);                                      \
    cpa16(_sb + so[3], Xh + go[3] + _kt);                                      \
    cpa16(_sb + TILEB + so[0], Wh + go[0] + _kt);                              \
    cpa16(_sb + TILEB + so[1], Wh + go[1] + _kt);                              \
    cpa16(_sb + TILEB + so[2], Wh + go[2] + _kt);                              \
    cpa16(_sb + TILEB + so[3], Wh + go[3] + _kt);                              \
  } while (0)

  // fragment offsets: addr(ks) = off ^ (ks<<5). (XOR stays in bits 4..6:
  // off = row*128 + (chalf ^ ((row&7)<<4)); ks*32 toggles bits 5-6.)
  const int rl = lane & 15;
  const int chalf = (lane >> 4) * 16;
  uint32_t offA[4], offB[2];
#pragma unroll
  for (int mi = 0; mi < 4; mi++) {
    int row = warp_m0 + mi * 16 + rl;
    offA[mi] = (uint32_t)(row * 128 + (chalf ^ ((row & 7) << 4)));
  }
#pragma unroll
  for (int np = 0; np < 2; np++) {
    int row = warp_n0 + np * 16 + rl;
    offB[np] =
        TILEB + (uint32_t)(row * 128 + (chalf ^ ((row & 7) << 4)));
  }

  float acc[4][4][4];
#pragma unroll
  for (int i = 0; i < 4; i++)
#pragma unroll
    for (int j = 0; j < 4; j++)
#pragma unroll
      for (int e = 0; e < 4; e++) acc[i][j][e] = 0.f;

  // prologue: stages 0,1
  LOAD_STAGE(sbase, 0);
  asm volatile("cp.async.commit_group;" ::: "memory");
  LOAD_STAGE(sbase + STAGEB, BK);
  asm volatile("cp.async.commit_group;" ::: "memory");

  int slot = 0, wslot = 2;
  for (int k = 0; k < NK; k++) {
    asm volatile("cp.async.wait_group 1;" ::: "memory");
    __syncthreads();

    if (k + 2 < NK) LOAD_STAGE(sbase + wslot * STAGEB, (k + 2) * BK);
    asm volatile("cp.async.commit_group;" ::: "memory");

    const uint32_t sb = sbase + slot * STAGEB;
#pragma unroll
    for (int ks = 0; ks < 4; ks++) {
      const uint32_t kx = (uint32_t)(ks << 5);
      uint32_t bh[2][4], af[4][4];
      ldsm4(bh[0], sb + (offB[0] ^ kx));
      ldsm4(bh[1], sb + (offB[1] ^ kx));
#pragma unroll
      for (int mi = 0; mi < 4; mi++) ldsm4(af[mi], sb + (offA[mi] ^ kx));
#pragma unroll
      for (int mi = 0; mi < 4; mi++)
#pragma unroll
        for (int ni = 0; ni < 4; ni++)
          mma_f16(acc[mi][ni], af[mi], bh[ni >> 1][ni & 1],
                  bh[ni >> 1][2 + (ni & 1)]);
    }

    slot = (slot == 2) ? 0 : slot + 1;
    wslot = (wslot == 2) ? 0 : wslot + 1;
  }

  // ---- epilogue: LoRA + store ----
  asm volatile("cp.async.wait_all;" ::: "memory");
  __syncthreads();

  float* axs = (float*)sm;                    // [128][16]
  float* bs = (float*)(sm + 128 * 16 * 4);    // [128] stride 17
  for (int j = tid; j < TM * R_DIM; j += 256)
    axs[j] = g_ax[(size_t)m0 * R_DIM + j];
  for (int j = tid; j < TN * R_DIM; j += 256) {
    int col = j >> 4, r = j & 15;
    bs[col * 17 + r] = Bw[(size_t)(n0 + col) * R_DIM + r];
  }
  __syncthreads();

  const int r0 = lane >> 2;
  const int cbase = warp_n0 + (lane & 3) * 2;
#pragma unroll
  for (int mi = 0; mi < 4; mi++) {
#pragma unroll
    for (int half = 0; half < 2; half++) {
      const int mr = warp_m0 + mi * 16 + r0 + half * 8;
      float axr[16];
      *(float4*)&axr[0] = *(const float4*)&axs[mr * 16];
      *(float4*)&axr[4] = *(const float4*)&axs[mr * 16 + 4];
      *(float4*)&axr[8] = *(const float4*)&axs[mr * 16 + 8];
      *(float4*)&axr[12] = *(const float4*)&axs[mr * 16 + 12];
      float* orow = out + (size_t)(m0 + mr) * N_DIM + n0;
#pragma unroll
      for (int ni = 0; ni < 4; ni++) {
        const int c = cbase + ni * 8;
        const float* b0 = &bs[c * 17];
        const float* b1 = &bs[(c + 1) * 17];
        float l0 = 0.f, l1 = 0.f;
#pragma unroll
        for (int r = 0; r < 16; r++) {
          l0 += axr[r] * b0[r];
          l1 += axr[r] * b1[r];
        }
        float2 v = make_float2(acc[mi][ni][half * 2 + 0] + l0,
                               acc[mi][ni][half * 2 + 1] + l1);
        *(float2*)&orow[c] = v;
      }
    }
  }
}

// ---------------------------------------------------------------------------
extern "C" void kernel_launch(void* const* d_in, const int* in_sizes, int n_in,
                              void* d_out, int out_size) {
  const float* x = (const float*)d_in[0];
  const int* codes = (const int*)d_in[1];
  const float* absmax = (const float*)d_in[2];
  const float* A = (const float*)d_in[3];
  const float* Bw = (const float*)d_in[4];
  float* out = (float*)d_out;

  cudaFuncSetAttribute(qlora_mma_kernel,
                       cudaFuncAttributeMaxDynamicSharedMemorySize, SMEMB);

  split_x_kernel<<<(M_DIM * (size_t)K_DIM) / 1024, 256>>>(x);
  dequant_kernel<<<(N_DIM * (size_t)K_DIM) / 1024, 256>>>(codes, absmax);
  lora_ax_kernel<<<M_DIM / 32, 256>>>(x, A);

  dim3 grid(N_DIM / TN, M_DIM / TM);
  qlora_mma_kernel<<<grid, 256, SMEMB>>>(Bw, out);
}

// round 7
// speedup vs baseline: 6.5616x; 1.5795x over previous
#include <cuda_runtime.h>
#include <cuda_fp16.h>
#include <cstdint>

// QLoRA linear via mma.sync fp16 single-term GEMM:
// out = fp16(x) @ fp16(dequant_nf4(w))^T  (fp32 accum)  + 2.0*(x@A^T)@B^T

#define M_DIM 8192
#define N_DIM 4096
#define K_DIM 4096
#define R_DIM 16
#define TM 128
#define TN 128
#define BK 64
#define NK (K_DIM / BK)   // 64

#define TILEB 16384           // 128 rows x 128B (swizzled, SW128)
#define STAGEB (2 * TILEB)    // X, W = 32768
#define NSTG 3
#define SMEMB (NSTG * STAGEB) // 98304

#define KSPL 8
#define KS_LEN (K_DIM / KSPL)  // 512

// ---- device scratch ----
__device__ float g_ax[M_DIM * R_DIM];
__device__ float g_axp[M_DIM * R_DIM * KSPL];
__device__ __half g_xh[(size_t)M_DIM * K_DIM];
__device__ __half g_wh[(size_t)N_DIM * K_DIM];

__constant__ float c_nf4[16] = {
    -1.0f, -0.6961928009986877f, -0.5250730514526367f, -0.39491748809814453f,
    -0.28444138169288635f, -0.18477343022823334f, -0.09105003625154495f, 0.0f,
    0.07958029955625534f, 0.16093020141124725f, 0.24611230194568634f,
    0.33791524171829224f, 0.44070982933044434f, 0.5626170039176941f,
    0.7229568362236023f, 1.0f};

// ---------------------------------------------------------------------------
__device__ __forceinline__ uint32_t smem_u32(const void* p) {
  return (uint32_t)__cvta_generic_to_shared((void*)p);
}
__device__ __forceinline__ uint32_t swz(uint32_t off) {
  return off ^ (((off >> 7) & 7u) << 4);
}
__device__ __forceinline__ void cpa16(uint32_t s, const void* g) {
  asm volatile("cp.async.cg.shared.global [%0], [%1], 16;" :: "r"(s), "l"(g));
}
__device__ __forceinline__ void ldsm4(uint32_t (&r)[4], uint32_t addr) {
  asm volatile(
      "ldmatrix.sync.aligned.m8n8.x4.shared.b16 {%0,%1,%2,%3}, [%4];"
      : "=r"(r[0]), "=r"(r[1]), "=r"(r[2]), "=r"(r[3]) : "r"(addr));
}
__device__ __forceinline__ void mma_f16(float (&d)[4], const uint32_t (&a)[4],
                                        uint32_t b0, uint32_t b1) {
  asm volatile(
      "mma.sync.aligned.m16n8k16.row.col.f32.f16.f16.f32 "
      "{%0,%1,%2,%3}, {%4,%5,%6,%7}, {%8,%9}, {%0,%1,%2,%3};"
      : "+f"(d[0]), "+f"(d[1]), "+f"(d[2]), "+f"(d[3])
      : "r"(a[0]), "r"(a[1]), "r"(a[2]), "r"(a[3]), "r"(b0), "r"(b1));
}

// ---------------------------------------------------------------------------
// Precompute kernels
// ---------------------------------------------------------------------------
__global__ __launch_bounds__(256) void split_x_kernel(
    const float* __restrict__ x) {
  size_t i4 = (size_t)blockIdx.x * 256 + threadIdx.x;
  float4 v = ((const float4*)x)[i4];
  __half h[4] = {__float2half_rn(v.x), __float2half_rn(v.y),
                 __float2half_rn(v.z), __float2half_rn(v.w)};
  *(uint2*)&g_xh[i4 * 4] = *(uint2*)h;
}

__global__ __launch_bounds__(256) void dequant_kernel(
    const int* __restrict__ codes, const float* __restrict__ absmax) {
  __shared__ float lut[16];
  if (threadIdx.x < 16) lut[threadIdx.x] = c_nf4[threadIdx.x];
  __syncthreads();
  size_t i4 = (size_t)blockIdx.x * 256 + threadIdx.x;
  int4 c = ((const int4*)codes)[i4];
  size_t e0 = i4 * 4;
  int row = (int)(e0 >> 12);
  int col = (int)(e0 & 4095);
  float am = absmax[row * (K_DIM / 64) + (col >> 6)];
  __half h[4] = {__float2half_rn(lut[c.x] * am), __float2half_rn(lut[c.y] * am),
                 __float2half_rn(lut[c.z] * am), __float2half_rn(lut[c.w] * am)};
  *(uint2*)&g_wh[e0] = *(uint2*)h;
}

// partial lora: g_axp[(m*16+r)*KSPL + ks] = sum over this k-split
__global__ __launch_bounds__(256) void lora_axp_kernel(
    const float* __restrict__ x, const float* __restrict__ A) {
  __shared__ float Xc[32][65];
  __shared__ float Ac[64][16];
  const int tid = threadIdx.x;
  const int m0 = blockIdx.x * 32;
  const int ks = blockIdx.y;
  const int k0 = ks * KS_LEN;
  const int r = tid & 15;
  const int ml = tid >> 4;
  float acc0 = 0.f, acc1 = 0.f;
  for (int kc = k0; kc < k0 + KS_LEN; kc += 64) {
#pragma unroll
    for (int i = 0; i < 8; i++) {
      int idx = tid + i * 256;
      Xc[idx >> 6][idx & 63] =
          x[(size_t)(m0 + (idx >> 6)) * K_DIM + kc + (idx & 63)];
    }
#pragma unroll
    for (int i = 0; i < 4; i++) {
      int idx = tid + i * 256;
      Ac[idx >> 4][idx & 15] = A[(idx & 15) * K_DIM + kc + (idx >> 4)];
    }
    __syncthreads();
#pragma unroll 8
    for (int kk = 0; kk < 64; kk++) {
      float av = Ac[kk][r];
      acc0 += Xc[ml][kk] * av;
      acc1 += Xc[ml + 16][kk] * av;
    }
    __syncthreads();
  }
  g_axp[((size_t)(m0 + ml) * R_DIM + r) * KSPL + ks] = acc0;
  g_axp[((size_t)(m0 + ml + 16) * R_DIM + r) * KSPL + ks] = acc1;
}

__global__ __launch_bounds__(256) void lora_ax_reduce_kernel() {
  int j = blockIdx.x * 256 + threadIdx.x;  // 0 .. M*R-1
  const float4* p = (const float4*)&g_axp[(size_t)j * KSPL];
  float4 a = p[0], b = p[1];
  g_ax[j] = 2.0f * (((a.x + a.y) + (a.z + a.w)) + ((b.x + b.y) + (b.z + b.w)));
}

// ---------------------------------------------------------------------------
// Main HMMA GEMM: 128x128 tile, BK=64, 3-stage cp.async pipeline, SW128 smem
// ---------------------------------------------------------------------------
__global__ __launch_bounds__(256, 2) void qlora_mma_kernel(
    const float* __restrict__ Bw, float* __restrict__ out) {
  extern __shared__ char sm[];
  const int tid = threadIdx.x;
  const int wid = tid >> 5;
  const int lane = tid & 31;
  const int n0 = blockIdx.x * TN;
  const int m0 = blockIdx.y * TM;
  const int warp_m0 = (wid >> 2) * 64;
  const int warp_n0 = (wid & 3) * 32;
  const uint32_t sbase = smem_u32(sm);

  const __half* Xh = g_xh + (size_t)m0 * K_DIM;
  const __half* Wh = g_wh + (size_t)n0 * K_DIM;

  uint32_t so[4];
  size_t go[4];
#pragma unroll
  for (int j = 0; j < 4; j++) {
    int c = tid + j * 256;
    int row = c >> 3, cc = c & 7;
    go[j] = (size_t)row * K_DIM + cc * 8;
    so[j] = swz((uint32_t)(row * 128 + cc * 16));
  }

#define LOAD_STAGE(SB, KT)                                                     \
  do {                                                                         \
    uint32_t _sb = (SB);                                                       \
    int _kt = (KT);                                                            \
    cpa16(_sb + so[0], Xh + go[0] + _kt);                                      \
    cpa16(_sb + so[1], Xh + go[1] + _kt);                                      \
    cpa16(_sb + so[2], Xh + go[2] + _kt);                                      \
    cpa16(_sb + so[3], Xh + go[3] + _kt);                                      \
    cpa16(_sb + TILEB + so[0], Wh + go[0] + _kt);                              \
    cpa16(_sb + TILEB + so[1], Wh + go[1] + _kt);                              \
    cpa16(_sb + TILEB + so[2], Wh + go[2] + _kt);                              \
    cpa16(_sb + TILEB + so[3], Wh + go[3] + _kt);                              \
  } while (0)

  const int rl = lane & 15;
  const int chalf = (lane >> 4) * 16;
  uint32_t offA[4], offB[2];
#pragma unroll
  for (int mi = 0; mi < 4; mi++) {
    int row = warp_m0 + mi * 16 + rl;
    offA[mi] = (uint32_t)(row * 128 + (chalf ^ ((row & 7) << 4)));
  }
#pragma unroll
  for (int np = 0; np < 2; np++) {
    int row = warp_n0 + np * 16 + rl;
    offB[np] = TILEB + (uint32_t)(row * 128 + (chalf ^ ((row & 7) << 4)));
  }

  float acc[4][4][4];
#pragma unroll
  for (int i = 0; i < 4; i++)
#pragma unroll
    for (int j = 0; j < 4; j++)
#pragma unroll
      for (int e = 0; e < 4; e++) acc[i][j][e] = 0.f;

  LOAD_STAGE(sbase, 0);
  asm volatile("cp.async.commit_group;" ::: "memory");
  LOAD_STAGE(sbase + STAGEB, BK);
  asm volatile("cp.async.commit_group;" ::: "memory");

  int slot = 0, wslot = 2;
  for (int k = 0; k < NK; k++) {
    asm volatile("cp.async.wait_group 1;" ::: "memory");
    __syncthreads();

    if (k + 2 < NK) LOAD_STAGE(sbase + wslot * STAGEB, (k + 2) * BK);
    asm volatile("cp.async.commit_group;" ::: "memory");

    const uint32_t sb = sbase + slot * STAGEB;
#pragma unroll
    for (int ks = 0; ks < 4; ks++) {
      const uint32_t kx = (uint32_t)(ks << 5);
      uint32_t bh[2][4], af[4][4];
      ldsm4(bh[0], sb + (offB[0] ^ kx));
      ldsm4(bh[1], sb + (offB[1] ^ kx));
#pragma unroll
      for (int mi = 0; mi < 4; mi++) ldsm4(af[mi], sb + (offA[mi] ^ kx));
#pragma unroll
      for (int mi = 0; mi < 4; mi++)
#pragma unroll
        for (int ni = 0; ni < 4; ni++)
          mma_f16(acc[mi][ni], af[mi], bh[ni >> 1][ni & 1],
                  bh[ni >> 1][2 + (ni & 1)]);
    }

    slot = (slot == 2) ? 0 : slot + 1;
    wslot = (wslot == 2) ? 0 : wslot + 1;
  }

  // ---- epilogue: LoRA + store ----
  asm volatile("cp.async.wait_all;" ::: "memory");
  __syncthreads();

  float* axs = (float*)sm;                    // [128][16]
  float* bs = (float*)(sm + 128 * 16 * 4);    // [128] stride 17
  for (int j = tid; j < TM * R_DIM; j += 256)
    axs[j] = g_ax[(size_t)m0 * R_DIM + j];
  for (int j = tid; j < TN * R_DIM; j += 256) {
    int col = j >> 4, r = j & 15;
    bs[col * 17 + r] = Bw[(size_t)(n0 + col) * R_DIM + r];
  }
  __syncthreads();

  const int r0 = lane >> 2;
  const int cbase = warp_n0 + (lane & 3) * 2;
#pragma unroll
  for (int mi = 0; mi < 4; mi++) {
#pragma unroll
    for (int half = 0; half < 2; half++) {
      const int mr = warp_m0 + mi * 16 + r0 + half * 8;
      float axr[16];
      *(float4*)&axr[0] = *(const float4*)&axs[mr * 16];
      *(float4*)&axr[4] = *(const float4*)&axs[mr * 16 + 4];
      *(float4*)&axr[8] = *(const float4*)&axs[mr * 16 + 8];
      *(float4*)&axr[12] = *(const float4*)&axs[mr * 16 + 12];
      float* orow = out + (size_t)(m0 + mr) * N_DIM + n0;
#pragma unroll
      for (int ni = 0; ni < 4; ni++) {
        const int c = cbase + ni * 8;
        const float* b0 = &bs[c * 17];
        const float* b1 = &bs[(c + 1) * 17];
        float l0 = 0.f, l1 = 0.f;
#pragma unroll
        for (int r = 0; r < 16; r++) {
          l0 += axr[r] * b0[r];
          l1 += axr[r] * b1[r];
        }
        float2 v = make_float2(acc[mi][ni][half * 2 + 0] + l0,
                               acc[mi][ni][half * 2 + 1] + l1);
        *(float2*)&orow[c] = v;
      }
    }
  }
}

// ---------------------------------------------------------------------------
extern "C" void kernel_launch(void* const* d_in, const int* in_sizes, int n_in,
                              void* d_out, int out_size) {
  const float* x = (const float*)d_in[0];
  const int* codes = (const int*)d_in[1];
  const float* absmax = (const float*)d_in[2];
  const float* A = (const float*)d_in[3];
  const float* Bw = (const float*)d_in[4];
  float* out = (float*)d_out;

  cudaFuncSetAttribute(qlora_mma_kernel,
                       cudaFuncAttributeMaxDynamicSharedMemorySize, SMEMB);

  split_x_kernel<<<(M_DIM * (size_t)K_DIM) / 1024, 256>>>(x);
  dequant_kernel<<<(N_DIM * (size_t)K_DIM) / 1024, 256>>>(codes, absmax);
  {
    dim3 lgrid(M_DIM / 32, KSPL);
    lora_axp_kernel<<<lgrid, 256>>>(x, A);
    lora_ax_reduce_kernel<<<(M_DIM * R_DIM) / 256, 256>>>();
  }

  dim3 grid(N_DIM / TN, M_DIM / TM);
  qlora_mma_kernel<<<grid, 256, SMEMB>>>(Bw, out);
}

// round 8
// speedup vs baseline: 6.7093x; 1.0225x over previous
#include <cuda_runtime.h>
#include <cuda_fp16.h>
#include <cstdint>

// QLoRA linear via mma.sync fp16 single-term GEMM:
// out = fp16(x) @ fp16(dequant_nf4(w))^T  (fp32 accum)  + 2.0*(x@A^T)@B^T

#define M_DIM 8192
#define N_DIM 4096
#define K_DIM 4096
#define R_DIM 16
#define TM 128
#define TN 128
#define BK 64
#define NK (K_DIM / BK)   // 64

#define TILEB 16384           // 128 rows x 128B (swizzled, SW128)
#define STAGEB (2 * TILEB)    // X, W = 32768
#define NSTG 3
#define SMEMB (NSTG * STAGEB) // 98304

#define KSPL 8
#define KS_LEN (K_DIM / KSPL)  // 512

// ---- device scratch ----
__device__ float g_ax[M_DIM * R_DIM];
__device__ float g_axp[M_DIM * R_DIM * KSPL];
__device__ __half g_xh[(size_t)M_DIM * K_DIM];
__device__ __half g_wh[(size_t)N_DIM * K_DIM];

__constant__ float c_nf4[16] = {
    -1.0f, -0.6961928009986877f, -0.5250730514526367f, -0.39491748809814453f,
    -0.28444138169288635f, -0.18477343022823334f, -0.09105003625154495f, 0.0f,
    0.07958029955625534f, 0.16093020141124725f, 0.24611230194568634f,
    0.33791524171829224f, 0.44070982933044434f, 0.5626170039176941f,
    0.7229568362236023f, 1.0f};

// ---------------------------------------------------------------------------
__device__ __forceinline__ uint32_t smem_u32(const void* p) {
  return (uint32_t)__cvta_generic_to_shared((void*)p);
}
__device__ __forceinline__ uint32_t swz(uint32_t off) {
  return off ^ (((off >> 7) & 7u) << 4);
}
__device__ __forceinline__ void cpa16(uint32_t s, const void* g) {
  asm volatile("cp.async.cg.shared.global [%0], [%1], 16;" :: "r"(s), "l"(g));
}
__device__ __forceinline__ void ldsm4(uint32_t (&r)[4], uint32_t addr) {
  asm volatile(
      "ldmatrix.sync.aligned.m8n8.x4.shared.b16 {%0,%1,%2,%3}, [%4];"
      : "=r"(r[0]), "=r"(r[1]), "=r"(r[2]), "=r"(r[3]) : "r"(addr));
}
__device__ __forceinline__ void mma_f16(float (&d)[4], const uint32_t (&a)[4],
                                        uint32_t b0, uint32_t b1) {
  asm volatile(
      "mma.sync.aligned.m16n8k16.row.col.f32.f16.f16.f32 "
      "{%0,%1,%2,%3}, {%4,%5,%6,%7}, {%8,%9}, {%0,%1,%2,%3};"
      : "+f"(d[0]), "+f"(d[1]), "+f"(d[2]), "+f"(d[3])
      : "r"(a[0]), "r"(a[1]), "r"(a[2]), "r"(a[3]), "r"(b0), "r"(b1));
}

// ---------------------------------------------------------------------------
// Precompute kernels
// ---------------------------------------------------------------------------
__global__ __launch_bounds__(256) void dequant_kernel(
    const int* __restrict__ codes, const float* __restrict__ absmax) {
  __shared__ float lut[16];
  if (threadIdx.x < 16) lut[threadIdx.x] = c_nf4[threadIdx.x];
  __syncthreads();
  size_t i4 = (size_t)blockIdx.x * 256 + threadIdx.x;
  int4 c = ((const int4*)codes)[i4];
  size_t e0 = i4 * 4;
  int row = (int)(e0 >> 12);
  int col = (int)(e0 & 4095);
  float am = absmax[row * (K_DIM / 64) + (col >> 6)];
  __half h[4] = {__float2half_rn(lut[c.x] * am), __float2half_rn(lut[c.y] * am),
                 __float2half_rn(lut[c.z] * am), __float2half_rn(lut[c.w] * am)};
  *(uint2*)&g_wh[e0] = *(uint2*)h;
}

// partial lora + fused x->fp16 conversion.
// Grid (M/32, KSPL) covers every x element exactly once -> write g_xh here.
__global__ __launch_bounds__(256) void lora_axp_kernel(
    const float* __restrict__ x, const float* __restrict__ A) {
  __shared__ float Xc[32][65];
  __shared__ float Ac[64][16];
  const int tid = threadIdx.x;
  const int m0 = blockIdx.x * 32;
  const int ks = blockIdx.y;
  const int k0 = ks * KS_LEN;
  const int r = tid & 15;
  const int ml = tid >> 4;
  float acc0 = 0.f, acc1 = 0.f;
  for (int kc = k0; kc < k0 + KS_LEN; kc += 64) {
#pragma unroll
    for (int i = 0; i < 8; i++) {
      int idx = tid + i * 256;
      int row = idx >> 6, col = idx & 63;
      size_t gofs = (size_t)(m0 + row) * K_DIM + kc + col;
      float v = x[gofs];
      Xc[row][col] = v;
      g_xh[gofs] = __float2half_rn(v);
    }
#pragma unroll
    for (int i = 0; i < 4; i++) {
      int idx = tid + i * 256;
      Ac[idx >> 4][idx & 15] = A[(idx & 15) * K_DIM + kc + (idx >> 4)];
    }
    __syncthreads();
#pragma unroll 8
    for (int kk = 0; kk < 64; kk++) {
      float av = Ac[kk][r];
      acc0 += Xc[ml][kk] * av;
      acc1 += Xc[ml + 16][kk] * av;
    }
    __syncthreads();
  }
  g_axp[((size_t)(m0 + ml) * R_DIM + r) * KSPL + ks] = acc0;
  g_axp[((size_t)(m0 + ml + 16) * R_DIM + r) * KSPL + ks] = acc1;
}

__global__ __launch_bounds__(256) void lora_ax_reduce_kernel() {
  int j = blockIdx.x * 256 + threadIdx.x;  // 0 .. M*R-1
  const float4* p = (const float4*)&g_axp[(size_t)j * KSPL];
  float4 a = p[0], b = p[1];
  g_ax[j] = 2.0f * (((a.x + a.y) + (a.z + a.w)) + ((b.x + b.y) + (b.z + b.w)));
}

// ---------------------------------------------------------------------------
// Main HMMA GEMM: 128x128 tile, BK=64, 3-stage cp.async pipeline, SW128 smem,
// B-fragment register double-buffer across ks-subtiles.
// ---------------------------------------------------------------------------
__global__ __launch_bounds__(256, 2) void qlora_mma_kernel(
    const float* __restrict__ Bw, float* __restrict__ out) {
  extern __shared__ char sm[];
  const int tid = threadIdx.x;
  const int wid = tid >> 5;
  const int lane = tid & 31;
  const int n0 = blockIdx.x * TN;
  const int m0 = blockIdx.y * TM;
  const int warp_m0 = (wid >> 2) * 64;
  const int warp_n0 = (wid & 3) * 32;
  const uint32_t sbase = smem_u32(sm);

  const __half* Xh = g_xh + (size_t)m0 * K_DIM;
  const __half* Wh = g_wh + (size_t)n0 * K_DIM;

  uint32_t so[4];
  size_t go[4];
#pragma unroll
  for (int j = 0; j < 4; j++) {
    int c = tid + j * 256;
    int row = c >> 3, cc = c & 7;
    go[j] = (size_t)row * K_DIM + cc * 8;
    so[j] = swz((uint32_t)(row * 128 + cc * 16));
  }

#define LOAD_STAGE(SB, KT)                                                     \
  do {                                                                         \
    uint32_t _sb = (SB);                                                       \
    int _kt = (KT);                                                            \
    cpa16(_sb + so[0], Xh + go[0] + _kt);                                      \
    cpa16(_sb + so[1], Xh + go[1] + _kt);                                      \
    cpa16(_sb + so[2], Xh + go[2] + _kt);                                      \
    cpa16(_sb + so[3], Xh + go[3] + _kt);                                      \
    cpa16(_sb + TILEB + so[0], Wh + go[0] + _kt);                              \
    cpa16(_sb + TILEB + so[1], Wh + go[1] + _kt);                              \
    cpa16(_sb + TILEB + so[2], Wh + go[2] + _kt);                              \
    cpa16(_sb + TILEB + so[3], Wh + go[3] + _kt);                              \
  } while (0)

  const int rl = lane & 15;
  const int chalf = (lane >> 4) * 16;
  uint32_t offA[4], offB[2];
#pragma unroll
  for (int mi = 0; mi < 4; mi++) {
    int row = warp_m0 + mi * 16 + rl;
    offA[mi] = (uint32_t)(row * 128 + (chalf ^ ((row & 7) << 4)));
  }
#pragma unroll
  for (int np = 0; np < 2; np++) {
    int row = warp_n0 + np * 16 + rl;
    offB[np] = TILEB + (uint32_t)(row * 128 + (chalf ^ ((row & 7) << 4)));
  }

  float acc[4][4][4];
#pragma unroll
  for (int i = 0; i < 4; i++)
#pragma unroll
    for (int j = 0; j < 4; j++)
#pragma unroll
      for (int e = 0; e < 4; e++) acc[i][j][e] = 0.f;

  LOAD_STAGE(sbase, 0);
  asm volatile("cp.async.commit_group;" ::: "memory");
  LOAD_STAGE(sbase + STAGEB, BK);
  asm volatile("cp.async.commit_group;" ::: "memory");

  int slot = 0, wslot = 2;
  for (int k = 0; k < NK; k++) {
    asm volatile("cp.async.wait_group 1;" ::: "memory");
    __syncthreads();

    if (k + 2 < NK) LOAD_STAGE(sbase + wslot * STAGEB, (k + 2) * BK);
    asm volatile("cp.async.commit_group;" ::: "memory");

    const uint32_t sb = sbase + slot * STAGEB;

    // B fragments double-buffered across ks
    uint32_t bh[2][2][4];
    ldsm4(bh[0][0], sb + offB[0]);
    ldsm4(bh[0][1], sb + offB[1]);
#pragma unroll
    for (int ks = 0; ks < 4; ks++) {
      const uint32_t kx = (uint32_t)(ks << 5);
      const int cur = ks & 1;
      uint32_t af[4][4];
#pragma unroll
      for (int mi = 0; mi < 4; mi++) ldsm4(af[mi], sb + (offA[mi] ^ kx));
      if (ks < 3) {
        const uint32_t kxn = (uint32_t)((ks + 1) << 5);
        ldsm4(bh[cur ^ 1][0], sb + (offB[0] ^ kxn));
        ldsm4(bh[cur ^ 1][1], sb + (offB[1] ^ kxn));
      }
#pragma unroll
      for (int mi = 0; mi < 4; mi++)
#pragma unroll
        for (int ni = 0; ni < 4; ni++)
          mma_f16(acc[mi][ni], af[mi], bh[cur][ni >> 1][ni & 1],
                  bh[cur][ni >> 1][2 + (ni & 1)]);
    }

    slot = (slot == 2) ? 0 : slot + 1;
    wslot = (wslot == 2) ? 0 : wslot + 1;
  }

  // ---- epilogue: LoRA + store ----
  asm volatile("cp.async.wait_all;" ::: "memory");
  __syncthreads();

  float* axs = (float*)sm;                    // [128][16]
  float* bs = (float*)(sm + 128 * 16 * 4);    // [128] stride 17
  for (int j = tid; j < TM * R_DIM; j += 256)
    axs[j] = g_ax[(size_t)m0 * R_DIM + j];
  for (int j = tid; j < TN * R_DIM; j += 256) {
    int col = j >> 4, r = j & 15;
    bs[col * 17 + r] = Bw[(size_t)(n0 + col) * R_DIM + r];
  }
  __syncthreads();

  const int r0 = lane >> 2;
  const int cbase = warp_n0 + (lane & 3) * 2;
#pragma unroll
  for (int mi = 0; mi < 4; mi++) {
#pragma unroll
    for (int half = 0; half < 2; half++) {
      const int mr = warp_m0 + mi * 16 + r0 + half * 8;
      float axr[16];
      *(float4*)&axr[0] = *(const float4*)&axs[mr * 16];
      *(float4*)&axr[4] = *(const float4*)&axs[mr * 16 + 4];
      *(float4*)&axr[8] = *(const float4*)&axs[mr * 16 + 8];
      *(float4*)&axr[12] = *(const float4*)&axs[mr * 16 + 12];
      float* orow = out + (size_t)(m0 + mr) * N_DIM + n0;
#pragma unroll
      for (int ni = 0; ni < 4; ni++) {
        const int c = cbase + ni * 8;
        const float* b0 = &bs[c * 17];
        const float* b1 = &bs[(c + 1) * 17];
        float l0 = 0.f, l1 = 0.f;
#pragma unroll
        for (int r = 0; r < 16; r++) {
          l0 += axr[r] * b0[r];
          l1 += axr[r] * b1[r];
        }
        float2 v = make_float2(acc[mi][ni][half * 2 + 0] + l0,
                               acc[mi][ni][half * 2 + 1] + l1);
        *(float2*)&orow[c] = v;
      }
    }
  }
}

// ---------------------------------------------------------------------------
extern "C" void kernel_launch(void* const* d_in, const int* in_sizes, int n_in,
                              void* d_out, int out_size) {
  const float* x = (const float*)d_in[0];
  const int* codes = (const int*)d_in[1];
  const float* absmax = (const float*)d_in[2];
  const float* A = (const float*)d_in[3];
  const float* Bw = (const float*)d_in[4];
  float* out = (float*)d_out;

  cudaFuncSetAttribute(qlora_mma_kernel,
                       cudaFuncAttributeMaxDynamicSharedMemorySize, SMEMB);

  dequant_kernel<<<(N_DIM * (size_t)K_DIM) / 1024, 256>>>(codes, absmax);
  {
    dim3 lgrid(M_DIM / 32, KSPL);
    lora_axp_kernel<<<lgrid, 256>>>(x, A);
    lora_ax_reduce_kernel<<<(M_DIM * R_DIM) / 256, 256>>>();
  }

  dim3 grid(N_DIM / TN, M_DIM / TM);
  qlora_mma_kernel<<<grid, 256, SMEMB>>>(Bw, out);
}